// round 8
// baseline (speedup 1.0000x reference)
#include <cuda_runtime.h>
#include <math.h>

#define HH 256
#define WW 256
#define HWN 65536
#define PW 264
#define PS (258 * 264)

// ---------------- scratch (device globals; zero-initialized, halos never written) ----
__device__ float g_t0[64 * PS];
__device__ float g_t1[64 * PS];
__device__ float g_c3[216 * PS];    // conv4 raw output (padded layout)
__device__ float g_cat[128 * PS];   // mdcn outputs (padded; halos stay zero)
__device__ float g_wT[9 * 64 * 64];

// ---------------- conv 3x3, CIN=128, 1-cin steps ----------------
// BCHECK: input is unpadded [C,256,256] and staging bounds-checks (folds padding in).
// else: input is padded planes [C, 258, 264], interior at (+1,+1).
// PADOUT: write padded planes, else unpadded [C,256,256].
template <bool BCHECK, bool LRELU, bool PADOUT>
__global__ __launch_bounds__(128) void conv3x3_c128_kernel(
    const float* __restrict__ in, const float* __restrict__ wgt,
    const float* __restrict__ bias, float* __restrict__ out)
{
    __shared__ float s_in[2][18][66];
    __shared__ float s_w[128][8][9];

    const int tid = threadIdx.x;
    const int txg = tid & 7;
    const int ty = tid >> 3;
    const int x0 = blockIdx.x * 64;
    const int y0 = blockIdx.y * 16;
    const int coB = blockIdx.z * 8;

    for (int i = tid; i < 128 * 8 * 9; i += 128) {
        int co = i / (128 * 9);
        int r = i - co * (128 * 9);
        s_w[r / 9][co][r % 9] = wgt[(size_t)(coB + co) * (128 * 9) + r];
    }
    // stage ci=0
    for (int i = tid; i < 18 * 66; i += 128) {
        int r = i / 66, c = i - r * 66;
        float v;
        if (BCHECK) {
            int gy = y0 - 1 + r, gx = x0 - 1 + c;
            v = (gy >= 0 && gy < HH && gx >= 0 && gx < WW) ? in[(size_t)gy * WW + gx] : 0.f;
        } else {
            v = in[(size_t)(y0 + r) * PW + x0 + c];
        }
        s_in[0][r][c] = v;
    }
    __syncthreads();

    float acc[8][8];
#pragma unroll
    for (int o = 0; o < 8; o++)
#pragma unroll
        for (int p = 0; p < 8; p++) acc[o][p] = 0.f;

    const int xb = txg * 8;
    for (int ci = 0; ci < 128; ci++) {
        const int pb = ci & 1;
        if (ci + 1 < 128) {
            if (BCHECK) {
                const float* ip = in + (size_t)(ci + 1) * HWN;
                for (int i = tid; i < 18 * 66; i += 128) {
                    int r = i / 66, c = i - r * 66;
                    int gy = y0 - 1 + r, gx = x0 - 1 + c;
                    s_in[1 - pb][r][c] =
                        (gy >= 0 && gy < HH && gx >= 0 && gx < WW) ? ip[(size_t)gy * WW + gx] : 0.f;
                }
            } else {
                const float* ip = in + (size_t)(ci + 1) * PS;
                for (int i = tid; i < 18 * 66; i += 128) {
                    int r = i / 66, c = i - r * 66;
                    s_in[1 - pb][r][c] = ip[(size_t)(y0 + r) * PW + x0 + c];
                }
            }
        }
        float v[3][10];
#pragma unroll
        for (int r = 0; r < 3; r++)
#pragma unroll
            for (int c = 0; c < 10; c++) v[r][c] = s_in[pb][ty + r][xb + c];
#pragma unroll
        for (int o = 0; o < 8; o++) {
            float wr[9];
#pragma unroll
            for (int k = 0; k < 9; k++) wr[k] = s_w[ci][o][k];
#pragma unroll
            for (int p = 0; p < 8; p++) {
                float a = acc[o][p];
                a = fmaf(v[0][p + 0], wr[0], a);
                a = fmaf(v[0][p + 1], wr[1], a);
                a = fmaf(v[0][p + 2], wr[2], a);
                a = fmaf(v[1][p + 0], wr[3], a);
                a = fmaf(v[1][p + 1], wr[4], a);
                a = fmaf(v[1][p + 2], wr[5], a);
                a = fmaf(v[2][p + 0], wr[6], a);
                a = fmaf(v[2][p + 1], wr[7], a);
                a = fmaf(v[2][p + 2], wr[8], a);
                acc[o][p] = a;
            }
        }
        __syncthreads();
    }

    const int oy = y0 + ty;
    const int ox = x0 + xb;
#pragma unroll
    for (int o = 0; o < 8; o++) {
        float bb = bias[coB + o];
#pragma unroll
        for (int p = 0; p < 8; p++) {
            float r = acc[o][p] + bb;
            if (LRELU) r = (r >= 0.f) ? r : 0.1f * r;
            if (PADOUT)
                out[(size_t)(coB + o) * PS + (size_t)(oy + 1) * PW + ox + 1 + p] = r;
            else
                out[(size_t)(coB + o) * HWN + (size_t)oy * WW + ox + p] = r;
        }
    }
}

// ---------------- conv 3x3, CIN=64, 2-cin steps, padded in/out ----------------
template <bool LRELU>
__global__ __launch_bounds__(128) void conv3x3_c64_kernel(
    const float* __restrict__ in, const float* __restrict__ wgt,
    const float* __restrict__ bias, float* __restrict__ out)
{
    __shared__ float s_in[2][2][18][66];           // [buf][cc][r][c]
    __shared__ __align__(16) float s_w[64][8][12]; // padded to 12 for float4 loads

    const int tid = threadIdx.x;
    const int txg = tid & 7;
    const int ty = tid >> 3;
    const int x0 = blockIdx.x * 64;
    const int y0 = blockIdx.y * 16;
    const int coB = blockIdx.z * 8;

    for (int i = tid; i < 64 * 8 * 9; i += 128) {
        int co = i / (64 * 9);
        int r = i - co * (64 * 9);
        s_w[r / 9][co][r % 9] = wgt[(size_t)(coB + co) * (64 * 9) + r];
    }
    // stage ci pair 0 (channels 0,1)
    for (int i = tid; i < 2 * 18 * 66; i += 128) {
        int cc = i / (18 * 66);
        int r = (i - cc * 18 * 66) / 66, c = i % 66;
        s_in[0][cc][r][c] = in[(size_t)cc * PS + (size_t)(y0 + r) * PW + x0 + c];
    }
    __syncthreads();

    float acc[8][8];
#pragma unroll
    for (int o = 0; o < 8; o++)
#pragma unroll
        for (int p = 0; p < 8; p++) acc[o][p] = 0.f;

    const int xb = txg * 8;
    for (int cp = 0; cp < 32; cp++) {
        const int pb = cp & 1;
        if (cp + 1 < 32) {
            const float* ip = in + (size_t)(2 * cp + 2) * PS;
            for (int i = tid; i < 2 * 18 * 66; i += 128) {
                int cc = i / (18 * 66);
                int r = (i - cc * 18 * 66) / 66, c = i % 66;
                s_in[1 - pb][cc][r][c] = ip[(size_t)cc * PS + (size_t)(y0 + r) * PW + x0 + c];
            }
        }
#pragma unroll
        for (int cc = 0; cc < 2; cc++) {
            const int ci = 2 * cp + cc;
            float v[3][10];
#pragma unroll
            for (int r = 0; r < 3; r++)
#pragma unroll
                for (int c = 0; c < 10; c++) v[r][c] = s_in[pb][cc][ty + r][xb + c];
#pragma unroll
            for (int o = 0; o < 8; o++) {
                const float4* wv4 = reinterpret_cast<const float4*>(&s_w[ci][o][0]);
                float4 w0 = wv4[0], w1 = wv4[1], w2 = wv4[2];
#pragma unroll
                for (int p = 0; p < 8; p++) {
                    float a = acc[o][p];
                    a = fmaf(v[0][p + 0], w0.x, a);
                    a = fmaf(v[0][p + 1], w0.y, a);
                    a = fmaf(v[0][p + 2], w0.z, a);
                    a = fmaf(v[1][p + 0], w0.w, a);
                    a = fmaf(v[1][p + 1], w1.x, a);
                    a = fmaf(v[1][p + 2], w1.y, a);
                    a = fmaf(v[2][p + 0], w1.z, a);
                    a = fmaf(v[2][p + 1], w1.w, a);
                    a = fmaf(v[2][p + 2], w2.x, a);
                    acc[o][p] = a;
                }
            }
        }
        __syncthreads();
    }

    const int oy = y0 + ty;
    const int ox = x0 + xb;
#pragma unroll
    for (int o = 0; o < 8; o++) {
        float bb = bias[coB + o];
#pragma unroll
        for (int p = 0; p < 8; p++) {
            float r = acc[o][p] + bb;
            if (LRELU) r = (r >= 0.f) ? r : 0.1f * r;
            out[(size_t)(coB + o) * PS + (size_t)(oy + 1) * PW + ox + 1 + p] = r;
        }
    }
}

// ---------------- weight transpose for mdcn: wT[k][cin][o] = w[o][cin][k] ----------
__global__ void transpose_w_kernel(const float* __restrict__ wsrc, float* __restrict__ wT)
{
    int i = blockIdx.x * 256 + threadIdx.x;
    if (i < 9 * 4096) {
        int k = i / 4096;
        int r = i - k * 4096;
        int ci = r >> 6;
        int o = r & 63;
        wT[i] = wsrc[(size_t)(o * 64 + ci) * 9 + k];
    }
}

__device__ __forceinline__ float fast_tanh(float x)
{
    x = fminf(fmaxf(x, -15.f), 15.f);
    float e = __expf(2.f * x);
    return (e - 1.f) / (e + 1.f);
}

// ---------------- modulated deformable conv (fused offset transform) --------------
__global__ __launch_bounds__(128) void mdcn_kernel(
    const float* __restrict__ x,     // [64,256,256] feature (unpadded)
    const float* __restrict__ co,    // [216] padded planes
    const float* __restrict__ flow,  // [2,256,256]
    const float* __restrict__ wT,    // [9,64,64] (k,cin,o)
    const float* __restrict__ bias,  // [64]
    float* __restrict__ out)         // [64] padded planes
{
    __shared__ __align__(16) float s_w[4096];
    const int tid = threadIdx.x;
    const int px = blockIdx.x * 32 + (tid & 31);
    const int pyi = blockIdx.y * 4 + (tid >> 5);
    const int pix = pyi * WW + px;
    const int ppix = (pyi + 1) * PW + px + 1;

    const float f0 = flow[pix];
    const float f1 = flow[HWN + pix];

    float acc[64];
#pragma unroll
    for (int o = 0; o < 64; o++) acc[o] = 0.f;

#pragma unroll 1
    for (int k = 0; k < 9; k++) {
        __syncthreads();
        {
            const float4* src = reinterpret_cast<const float4*>(wT + (size_t)k * 4096);
            float4* dst = reinterpret_cast<float4*>(s_w);
            for (int i = tid; i < 1024; i += 128) dst[i] = src[i];
        }
        __syncthreads();
        const float kyf = (float)(k / 3 - 1);
        const float kxf = (float)(k % 3 - 1);
#pragma unroll 1
        for (int g = 0; g < 8; g++) {
            float oy = 10.f * fast_tanh(co[(size_t)(g * 18 + 2 * k) * PS + ppix]) + f1;
            float ox = 10.f * fast_tanh(co[(size_t)(g * 18 + 2 * k + 1) * PS + ppix]) + f0;
            float mr = co[(size_t)(144 + g * 9 + k) * PS + ppix];
            float mv = 1.f / (1.f + __expf(-mr));

            float pyf = (float)pyi + kyf + oy;
            float pxf = (float)px + kxf + ox;
            float y0f = floorf(pyf), x0f = floorf(pxf);
            float ly = pyf - y0f, lx = pxf - x0f;
            int iy0 = (int)y0f, ix0 = (int)x0f;
            int iy1 = iy0 + 1, ix1 = ix0 + 1;
            bool vy0 = (iy0 >= 0) & (iy0 < HH);
            bool vy1 = (iy1 >= 0) & (iy1 < HH);
            bool vx0 = (ix0 >= 0) & (ix0 < WW);
            bool vx1 = (ix1 >= 0) & (ix1 < WW);
            int cy0 = min(max(iy0, 0), HH - 1), cy1 = min(max(iy1, 0), HH - 1);
            int cx0 = min(max(ix0, 0), WW - 1), cx1 = min(max(ix1, 0), WW - 1);
            float w00 = (1.f - ly) * (1.f - lx) * mv;
            float w01 = (1.f - ly) * lx * mv;
            float w10 = ly * (1.f - lx) * mv;
            float w11 = ly * lx * mv;
            int i00 = cy0 * WW + cx0, i01 = cy0 * WW + cx1;
            int i10 = cy1 * WW + cx0, i11 = cy1 * WW + cx1;

#pragma unroll
            for (int c4 = 0; c4 < 2; c4++) {
                float v00[4], v01[4], v10[4], v11[4];
#pragma unroll
                for (int j = 0; j < 4; j++) {
                    const float* xc = x + (size_t)(g * 8 + c4 * 4 + j) * HWN;
                    v00[j] = (vy0 && vx0) ? xc[i00] : 0.f;
                    v01[j] = (vy0 && vx1) ? xc[i01] : 0.f;
                    v10[j] = (vy1 && vx0) ? xc[i10] : 0.f;
                    v11[j] = (vy1 && vx1) ? xc[i11] : 0.f;
                }
#pragma unroll
                for (int j = 0; j < 4; j++) {
                    float s = v00[j] * w00 + v01[j] * w01 + v10[j] * w10 + v11[j] * w11;
                    const float4* wp =
                        reinterpret_cast<const float4*>(&s_w[(g * 8 + c4 * 4 + j) * 64]);
#pragma unroll
                    for (int q = 0; q < 16; q++) {
                        float4 wv = wp[q];
                        acc[4 * q + 0] = fmaf(wv.x, s, acc[4 * q + 0]);
                        acc[4 * q + 1] = fmaf(wv.y, s, acc[4 * q + 1]);
                        acc[4 * q + 2] = fmaf(wv.z, s, acc[4 * q + 2]);
                        acc[4 * q + 3] = fmaf(wv.w, s, acc[4 * q + 3]);
                    }
                }
            }
        }
    }
#pragma unroll
    for (int o = 0; o < 64; o++) out[(size_t)o * PS + ppix] = acc[o] + bias[o];
}

// ---------------- launch ----------------
extern "C" void kernel_launch(void* const* d_in, const int* in_sizes, int n_in,
                              void* d_out, int out_size)
{
    (void)in_sizes; (void)n_in; (void)out_size;
    const float* feat_prev = (const float*)d_in[0];
    const float* feat_next = (const float*)d_in[1];
    const float* extra_prev = (const float*)d_in[2];
    const float* extra_next = (const float*)d_in[3];
    const float* flow_prev = (const float*)d_in[4];
    const float* flow_next = (const float*)d_in[5];
    const float* dcn1_w = (const float*)d_in[22];
    const float* dcn1_b = (const float*)d_in[23];
    const float* dcn2_w = (const float*)d_in[24];
    const float* dcn2_b = (const float*)d_in[25];
    const float* fus_w = (const float*)d_in[26];
    const float* fus_b = (const float*)d_in[27];
    float* out = (float*)d_out;

    float *t0, *t1, *c3, *cat, *wT;
    cudaGetSymbolAddress((void**)&t0, g_t0);
    cudaGetSymbolAddress((void**)&t1, g_t1);
    cudaGetSymbolAddress((void**)&c3, g_c3);
    cudaGetSymbolAddress((void**)&cat, g_cat);
    cudaGetSymbolAddress((void**)&wT, g_wT);

    dim3 blk(128);
    dim3 g64(4, 16, 8);
    dim3 g216(4, 16, 27);

    // both weight transposes first (launches 1-2) so ncu -s 5 captures conv4_0 (launch 6)
    transpose_w_kernel<<<144, 256>>>(dcn1_w, wT);                 // wT used per-branch; br0 first
    transpose_w_kernel<<<144, 256>>>(dcn1_w, wT);                 // placeholder slot (idempotent)

    for (int br = 0; br < 2; br++) {
        const float* feat = br == 0 ? feat_prev : feat_next;
        const float* extra = br == 0 ? extra_prev : extra_next;
        const float* flow = br == 0 ? flow_prev : flow_next;
        const float* w0 = (const float*)d_in[6 + 8 * br + 0];
        const float* b0 = (const float*)d_in[6 + 8 * br + 1];
        const float* w1 = (const float*)d_in[6 + 8 * br + 2];
        const float* b1 = (const float*)d_in[6 + 8 * br + 3];
        const float* w2 = (const float*)d_in[6 + 8 * br + 4];
        const float* b2 = (const float*)d_in[6 + 8 * br + 5];
        const float* w3 = (const float*)d_in[6 + 8 * br + 6];
        const float* b3 = (const float*)d_in[6 + 8 * br + 7];
        const float* dw = br == 0 ? dcn1_w : dcn2_w;
        const float* db = br == 0 ? dcn1_b : dcn2_b;

        conv3x3_c128_kernel<true, true, true><<<g64, blk>>>(extra, w0, b0, t0);
        conv3x3_c64_kernel<true><<<g64, blk>>>(t0, w1, b1, t1);
        conv3x3_c64_kernel<true><<<g64, blk>>>(t1, w2, b2, t0);
        conv3x3_c64_kernel<false><<<g216, blk>>>(t0, w3, b3, c3);
        transpose_w_kernel<<<144, 256>>>(dw, wT);
        mdcn_kernel<<<dim3(8, 64), blk>>>(feat, c3, flow, wT, db, cat + (size_t)br * 64 * PS);
    }
    conv3x3_c128_kernel<false, false, false><<<g64, blk>>>(cat, fus_w, fus_b, out);
}

// round 11
// speedup vs baseline: 1.1965x; 1.1965x over previous
#include <cuda_runtime.h>
#include <math.h>

#define HH 256
#define WW 256
#define HWN 65536
#define PW 264
#define PS (258 * 264)

// ---------------- scratch (device globals; zero-initialized, halos never written) ----
__device__ float g_t0[64 * PS];
__device__ float g_t1[64 * PS];
__device__ float g_c3[216 * PS];
__device__ float g_cat[128 * PS];
__device__ float g_wT[9 * 64 * 64];

// Stage one 18x34 tile from a padded plane (no bounds checks), incremental indices.
__device__ __forceinline__ void stage_tile_padded(
    float (*dst)[34], const float* __restrict__ src, int tid)
{
    int r = tid / 34;
    int c = tid - r * 34;
#pragma unroll
    for (int i = 0; i < 5; i++) {
        int idx = tid + i * 128;
        if (idx < 612) dst[r][c] = src[r * PW + c];
        r += 3; c += 26;
        if (c >= 34) { c -= 34; r += 1; }
    }
}

// Stage with bounds checks from an unpadded [256,256] plane (tile origin y0-1, x0-1).
__device__ __forceinline__ void stage_tile_checked(
    float (*dst)[34], const float* __restrict__ src, int y0, int x0, int tid)
{
    int r = tid / 34;
    int c = tid - r * 34;
#pragma unroll
    for (int i = 0; i < 5; i++) {
        int idx = tid + i * 128;
        if (idx < 612) {
            int gy = y0 - 1 + r, gx = x0 - 1 + c;
            dst[r][c] = (gy >= 0 && gy < HH && gx >= 0 && gx < WW) ? src[gy * WW + gx] : 0.f;
        }
        r += 3; c += 26;
        if (c >= 34) { c -= 34; r += 1; }
    }
}

// ---------------- conv 3x3, CIN=128 (R4 geometry: 32x16 tile, 4px x 8couts) ----------
template <bool BCHECK, bool LRELU, bool PADOUT>
__global__ __launch_bounds__(128) void conv3x3_c128_kernel(
    const float* __restrict__ in, const float* __restrict__ wgt,
    const float* __restrict__ bias, float* __restrict__ out)
{
    __shared__ float s_in[2][18][34];
    __shared__ float s_w[128][8][9];

    const int tid = threadIdx.x;
    const int tx = tid & 31;
    const int ty = tid >> 5;            // 0..3
    const int x0 = blockIdx.x * 32;
    const int y0 = blockIdx.y * 16;
    const int coB = blockIdx.z * 8;

    for (int i = tid; i < 128 * 8 * 9; i += 128) {
        int co = i / (128 * 9);
        int r = i - co * (128 * 9);
        s_w[r / 9][co][r % 9] = wgt[(coB + co) * (128 * 9) + r];
    }
    if (BCHECK) stage_tile_checked(s_in[0], in, y0, x0, tid);
    else        stage_tile_padded(s_in[0], in + y0 * PW + x0, tid);
    __syncthreads();

    float acc[4][8];
#pragma unroll
    for (int p = 0; p < 4; p++)
#pragma unroll
        for (int o = 0; o < 8; o++) acc[p][o] = 0.f;

    for (int ci = 0; ci < 128; ci++) {
        const int pb = ci & 1;
        if (ci + 1 < 128) {
            if (BCHECK) stage_tile_checked(s_in[1 - pb], in + (ci + 1) * HWN, y0, x0, tid);
            else        stage_tile_padded(s_in[1 - pb], in + (ci + 1) * PS + y0 * PW + x0, tid);
        }
        float v[4][3][3];
#pragma unroll
        for (int p = 0; p < 4; p++) {
            int ly = ty + 4 * p;
#pragma unroll
            for (int r = 0; r < 3; r++)
#pragma unroll
                for (int c = 0; c < 3; c++) v[p][r][c] = s_in[pb][ly + r][tx + c];
        }
#pragma unroll
        for (int o = 0; o < 8; o++) {
            float wr[9];
#pragma unroll
            for (int k = 0; k < 9; k++) wr[k] = s_w[ci][o][k];
#pragma unroll
            for (int p = 0; p < 4; p++) {
                float a = acc[p][o];
                a = fmaf(v[p][0][0], wr[0], a);
                a = fmaf(v[p][0][1], wr[1], a);
                a = fmaf(v[p][0][2], wr[2], a);
                a = fmaf(v[p][1][0], wr[3], a);
                a = fmaf(v[p][1][1], wr[4], a);
                a = fmaf(v[p][1][2], wr[5], a);
                a = fmaf(v[p][2][0], wr[6], a);
                a = fmaf(v[p][2][1], wr[7], a);
                a = fmaf(v[p][2][2], wr[8], a);
                acc[p][o] = a;
            }
        }
        __syncthreads();
    }

#pragma unroll
    for (int o = 0; o < 8; o++) {
        float bb = bias[coB + o];
#pragma unroll
        for (int p = 0; p < 4; p++) {
            float r = acc[p][o] + bb;
            if (LRELU) r = (r >= 0.f) ? r : 0.1f * r;
            int oy = y0 + ty + 4 * p;
            if (PADOUT)
                out[(coB + o) * PS + (oy + 1) * PW + x0 + tx + 1] = r;
            else
                out[(coB + o) * HWN + oy * WW + x0 + tx] = r;
        }
    }
}

// ---------------- conv 3x3, CIN=64 (R4 geometry; float4 weight loads) --------------
template <bool LRELU>
__global__ __launch_bounds__(128) void conv3x3_c64_kernel(
    const float* __restrict__ in, const float* __restrict__ wgt,
    const float* __restrict__ bias, float* __restrict__ out)
{
    __shared__ float s_in[2][18][34];
    __shared__ __align__(16) float s_w[64][8][12];

    const int tid = threadIdx.x;
    const int tx = tid & 31;
    const int ty = tid >> 5;
    const int x0 = blockIdx.x * 32;
    const int y0 = blockIdx.y * 16;
    const int coB = blockIdx.z * 8;

    for (int i = tid; i < 64 * 8 * 9; i += 128) {
        int co = i / (64 * 9);
        int r = i - co * (64 * 9);
        s_w[r / 9][co][r % 9] = wgt[(coB + co) * (64 * 9) + r];
    }
    stage_tile_padded(s_in[0], in + y0 * PW + x0, tid);
    __syncthreads();

    float acc[4][8];
#pragma unroll
    for (int p = 0; p < 4; p++)
#pragma unroll
        for (int o = 0; o < 8; o++) acc[p][o] = 0.f;

    for (int ci = 0; ci < 64; ci++) {
        const int pb = ci & 1;
        if (ci + 1 < 64)
            stage_tile_padded(s_in[1 - pb], in + (ci + 1) * PS + y0 * PW + x0, tid);

        float v[4][3][3];
#pragma unroll
        for (int p = 0; p < 4; p++) {
            int ly = ty + 4 * p;
#pragma unroll
            for (int r = 0; r < 3; r++)
#pragma unroll
                for (int c = 0; c < 3; c++) v[p][r][c] = s_in[pb][ly + r][tx + c];
        }
#pragma unroll
        for (int o = 0; o < 8; o++) {
            const float4* wv4 = reinterpret_cast<const float4*>(&s_w[ci][o][0]);
            float4 w0 = wv4[0], w1 = wv4[1], w2 = wv4[2];
#pragma unroll
            for (int p = 0; p < 4; p++) {
                float a = acc[p][o];
                a = fmaf(v[p][0][0], w0.x, a);
                a = fmaf(v[p][0][1], w0.y, a);
                a = fmaf(v[p][0][2], w0.z, a);
                a = fmaf(v[p][1][0], w0.w, a);
                a = fmaf(v[p][1][1], w1.x, a);
                a = fmaf(v[p][1][2], w1.y, a);
                a = fmaf(v[p][2][0], w1.z, a);
                a = fmaf(v[p][2][1], w1.w, a);
                a = fmaf(v[p][2][2], w2.x, a);
                acc[p][o] = a;
            }
        }
        __syncthreads();
    }

#pragma unroll
    for (int o = 0; o < 8; o++) {
        float bb = bias[coB + o];
#pragma unroll
        for (int p = 0; p < 4; p++) {
            float r = acc[p][o] + bb;
            if (LRELU) r = (r >= 0.f) ? r : 0.1f * r;
            int oy = y0 + ty + 4 * p;
            out[(coB + o) * PS + (oy + 1) * PW + x0 + tx + 1] = r;
        }
    }
}

// ---------------- weight transpose for mdcn: wT[k][cin][o] = w[o][cin][k] ----------
__global__ void transpose_w_kernel(const float* __restrict__ wsrc, float* __restrict__ wT)
{
    int i = blockIdx.x * 256 + threadIdx.x;
    if (i < 9 * 4096) {
        int k = i / 4096;
        int r = i - k * 4096;
        int ci = r >> 6;
        int o = r & 63;
        wT[i] = wsrc[(o * 64 + ci) * 9 + k];
    }
}

__device__ __forceinline__ float fast_tanh(float x)
{
    x = fminf(fmaxf(x, -15.f), 15.f);
    float e = __expf(2.f * x);
    return (e - 1.f) / (e + 1.f);
}

// ---------------- modulated deformable conv (fused offset transform) --------------
__global__ __launch_bounds__(128) void mdcn_kernel(
    const float* __restrict__ x,     // [64,256,256] feature (unpadded)
    const float* __restrict__ co,    // [216] padded planes
    const float* __restrict__ flow,  // [2,256,256]
    const float* __restrict__ wT,    // [9,64,64] (k,cin,o)
    const float* __restrict__ bias,  // [64]
    float* __restrict__ out)         // [64] padded planes
{
    __shared__ __align__(16) float s_w[4096];
    const int tid = threadIdx.x;
    const int px = blockIdx.x * 32 + (tid & 31);
    const int pyi = blockIdx.y * 4 + (tid >> 5);
    const int pix = pyi * WW + px;
    const int ppix = (pyi + 1) * PW + px + 1;

    const float f0 = flow[pix];
    const float f1 = flow[HWN + pix];

    float acc[64];
#pragma unroll
    for (int o = 0; o < 64; o++) acc[o] = 0.f;

#pragma unroll 1
    for (int k = 0; k < 9; k++) {
        __syncthreads();
        {
            const float4* src = reinterpret_cast<const float4*>(wT + k * 4096);
            float4* dst = reinterpret_cast<float4*>(s_w);
            for (int i = tid; i < 1024; i += 128) dst[i] = src[i];
        }
        __syncthreads();
        const float kyf = (float)(k / 3 - 1);
        const float kxf = (float)(k % 3 - 1);
#pragma unroll 1
        for (int g = 0; g < 8; g++) {
            float oy = 10.f * fast_tanh(co[(g * 18 + 2 * k) * PS + ppix]) + f1;
            float ox = 10.f * fast_tanh(co[(g * 18 + 2 * k + 1) * PS + ppix]) + f0;
            float mr = co[(144 + g * 9 + k) * PS + ppix];
            float mv = 1.f / (1.f + __expf(-mr));

            float pyf = (float)pyi + kyf + oy;
            float pxf = (float)px + kxf + ox;
            float y0f = floorf(pyf), x0f = floorf(pxf);
            float ly = pyf - y0f, lx = pxf - x0f;
            int iy0 = (int)y0f, ix0 = (int)x0f;
            int iy1 = iy0 + 1, ix1 = ix0 + 1;
            bool vy0 = (iy0 >= 0) & (iy0 < HH);
            bool vy1 = (iy1 >= 0) & (iy1 < HH);
            bool vx0 = (ix0 >= 0) & (ix0 < WW);
            bool vx1 = (ix1 >= 0) & (ix1 < WW);
            int cy0 = min(max(iy0, 0), HH - 1), cy1 = min(max(iy1, 0), HH - 1);
            int cx0 = min(max(ix0, 0), WW - 1), cx1 = min(max(ix1, 0), WW - 1);
            float w00 = (1.f - ly) * (1.f - lx) * mv;
            float w01 = (1.f - ly) * lx * mv;
            float w10 = ly * (1.f - lx) * mv;
            float w11 = ly * lx * mv;
            int i00 = cy0 * WW + cx0, i01 = cy0 * WW + cx1;
            int i10 = cy1 * WW + cx0, i11 = cy1 * WW + cx1;

#pragma unroll
            for (int c4 = 0; c4 < 2; c4++) {
                float v00[4], v01[4], v10[4], v11[4];
#pragma unroll
                for (int j = 0; j < 4; j++) {
                    const float* xc = x + (g * 8 + c4 * 4 + j) * HWN;
                    v00[j] = (vy0 && vx0) ? xc[i00] : 0.f;
                    v01[j] = (vy0 && vx1) ? xc[i01] : 0.f;
                    v10[j] = (vy1 && vx0) ? xc[i10] : 0.f;
                    v11[j] = (vy1 && vx1) ? xc[i11] : 0.f;
                }
#pragma unroll
                for (int j = 0; j < 4; j++) {
                    float s = v00[j] * w00 + v01[j] * w01 + v10[j] * w10 + v11[j] * w11;
                    const float4* wp =
                        reinterpret_cast<const float4*>(&s_w[(g * 8 + c4 * 4 + j) * 64]);
#pragma unroll
                    for (int q = 0; q < 16; q++) {
                        float4 wv = wp[q];
                        acc[4 * q + 0] = fmaf(wv.x, s, acc[4 * q + 0]);
                        acc[4 * q + 1] = fmaf(wv.y, s, acc[4 * q + 1]);
                        acc[4 * q + 2] = fmaf(wv.z, s, acc[4 * q + 2]);
                        acc[4 * q + 3] = fmaf(wv.w, s, acc[4 * q + 3]);
                    }
                }
            }
        }
    }
#pragma unroll
    for (int o = 0; o < 64; o++) out[o * PS + ppix] = acc[o] + bias[o];
}

// ---------------- launch ----------------
extern "C" void kernel_launch(void* const* d_in, const int* in_sizes, int n_in,
                              void* d_out, int out_size)
{
    (void)in_sizes; (void)n_in; (void)out_size;
    const float* feat_prev = (const float*)d_in[0];
    const float* feat_next = (const float*)d_in[1];
    const float* extra_prev = (const float*)d_in[2];
    const float* extra_next = (const float*)d_in[3];
    const float* flow_prev = (const float*)d_in[4];
    const float* flow_next = (const float*)d_in[5];
    const float* dcn1_w = (const float*)d_in[22];
    const float* dcn1_b = (const float*)d_in[23];
    const float* dcn2_w = (const float*)d_in[24];
    const float* dcn2_b = (const float*)d_in[25];
    const float* fus_w = (const float*)d_in[26];
    const float* fus_b = (const float*)d_in[27];
    float* out = (float*)d_out;

    float *t0, *t1, *c3, *cat, *wT;
    cudaGetSymbolAddress((void**)&t0, g_t0);
    cudaGetSymbolAddress((void**)&t1, g_t1);
    cudaGetSymbolAddress((void**)&c3, g_c3);
    cudaGetSymbolAddress((void**)&cat, g_cat);
    cudaGetSymbolAddress((void**)&wT, g_wT);

    dim3 blk(128);
    dim3 g64(8, 16, 8);
    dim3 g216(8, 16, 27);

    // transposes first so ncu -s 5 lands on a big conv
    transpose_w_kernel<<<144, 256>>>(dcn1_w, wT);
    transpose_w_kernel<<<144, 256>>>(dcn1_w, wT);

    for (int br = 0; br < 2; br++) {
        const float* feat = br == 0 ? feat_prev : feat_next;
        const float* extra = br == 0 ? extra_prev : extra_next;
        const float* flow = br == 0 ? flow_prev : flow_next;
        const float* w0 = (const float*)d_in[6 + 8 * br + 0];
        const float* b0 = (const float*)d_in[6 + 8 * br + 1];
        const float* w1 = (const float*)d_in[6 + 8 * br + 2];
        const float* b1 = (const float*)d_in[6 + 8 * br + 3];
        const float* w2 = (const float*)d_in[6 + 8 * br + 4];
        const float* b2 = (const float*)d_in[6 + 8 * br + 5];
        const float* w3 = (const float*)d_in[6 + 8 * br + 6];
        const float* b3 = (const float*)d_in[6 + 8 * br + 7];
        const float* dw = br == 0 ? dcn1_w : dcn2_w;
        const float* db = br == 0 ? dcn1_b : dcn2_b;

        conv3x3_c128_kernel<true, true, true><<<g64, blk>>>(extra, w0, b0, t0);
        conv3x3_c64_kernel<true><<<g64, blk>>>(t0, w1, b1, t1);
        conv3x3_c64_kernel<true><<<g64, blk>>>(t1, w2, b2, t0);
        conv3x3_c64_kernel<false><<<g216, blk>>>(t0, w3, b3, c3);
        transpose_w_kernel<<<144, 256>>>(dw, wT);
        mdcn_kernel<<<dim3(8, 64), blk>>>(feat, c3, flow, wT, db, cat + br * 64 * PS);
    }
    conv3x3_c128_kernel<false, false, false><<<g64, blk>>>(cat, fus_w, fus_b, out);
}

// round 14
// speedup vs baseline: 1.3431x; 1.1225x over previous
#include <cuda_runtime.h>
#include <math.h>

#define HH 256
#define WW 256
#define HWN 65536
#define PW 264
#define PS (258 * 264)

// ---------------- scratch (device globals; zero-initialized, halos never written) ----
__device__ float g_t0[64 * PS];
__device__ float g_t1[64 * PS];
__device__ float g_c3[216 * PS];
__device__ float g_cat[128 * PS];
__device__ float g_wT[9 * 64 * 64];

// Stage one 18x34 tile from a padded plane (no bounds checks), incremental indices.
__device__ __forceinline__ void stage_tile_padded(
    float (*dst)[34], const float* __restrict__ src, int tid)
{
    int r = tid / 34;
    int c = tid - r * 34;
#pragma unroll
    for (int i = 0; i < 5; i++) {
        int idx = tid + i * 128;
        if (idx < 612) dst[r][c] = src[r * PW + c];
        r += 3; c += 26;
        if (c >= 34) { c -= 34; r += 1; }
    }
}

// Stage with bounds checks from an unpadded [256,256] plane (tile origin y0-1, x0-1).
__device__ __forceinline__ void stage_tile_checked(
    float (*dst)[34], const float* __restrict__ src, int y0, int x0, int tid)
{
    int r = tid / 34;
    int c = tid - r * 34;
#pragma unroll
    for (int i = 0; i < 5; i++) {
        int idx = tid + i * 128;
        if (idx < 612) {
            int gy = y0 - 1 + r, gx = x0 - 1 + c;
            dst[r][c] = (gy >= 0 && gy < HH && gx >= 0 && gx < WW) ? src[gy * WW + gx] : 0.f;
        }
        r += 3; c += 26;
        if (c >= 34) { c -= 34; r += 1; }
    }
}

// ---------------- conv 3x3, CIN=128: 32x16 tile, 4 consecutive rows x 8 couts ------
template <bool BCHECK, bool LRELU, bool PADOUT>
__global__ __launch_bounds__(128) void conv3x3_c128_kernel(
    const float* __restrict__ in, const float* __restrict__ wgt,
    const float* __restrict__ bias, float* __restrict__ out)
{
    __shared__ float s_in[2][18][34];
    __shared__ float s_w[128][8][9];

    const int tid = threadIdx.x;
    const int tx = tid & 31;
    const int ty4 = (tid >> 5) * 4;     // base output row (0,4,8,12)
    const int x0 = blockIdx.x * 32;
    const int y0 = blockIdx.y * 16;
    const int coB = blockIdx.z * 8;

    for (int i = tid; i < 128 * 8 * 9; i += 128) {
        int co = i / (128 * 9);
        int r = i - co * (128 * 9);
        s_w[r / 9][co][r % 9] = wgt[(coB + co) * (128 * 9) + r];
    }
    if (BCHECK) stage_tile_checked(s_in[0], in, y0, x0, tid);
    else        stage_tile_padded(s_in[0], in + y0 * PW + x0, tid);
    __syncthreads();

    float acc[4][8];
#pragma unroll
    for (int p = 0; p < 4; p++)
#pragma unroll
        for (int o = 0; o < 8; o++) acc[p][o] = 0.f;

    for (int ci = 0; ci < 128; ci++) {
        const int pb = ci & 1;
        if (ci + 1 < 128) {
            if (BCHECK) stage_tile_checked(s_in[1 - pb], in + (ci + 1) * HWN, y0, x0, tid);
            else        stage_tile_padded(s_in[1 - pb], in + (ci + 1) * PS + y0 * PW + x0, tid);
        }
        // shared 6x3 window covers all 4 consecutive output rows
        float vv[6][3];
#pragma unroll
        for (int rr = 0; rr < 6; rr++)
#pragma unroll
            for (int c = 0; c < 3; c++) vv[rr][c] = s_in[pb][ty4 + rr][tx + c];
#pragma unroll
        for (int o = 0; o < 8; o++) {
            float wr[9];
#pragma unroll
            for (int k = 0; k < 9; k++) wr[k] = s_w[ci][o][k];
#pragma unroll
            for (int p = 0; p < 4; p++) {
                float a = acc[p][o];
                a = fmaf(vv[p + 0][0], wr[0], a);
                a = fmaf(vv[p + 0][1], wr[1], a);
                a = fmaf(vv[p + 0][2], wr[2], a);
                a = fmaf(vv[p + 1][0], wr[3], a);
                a = fmaf(vv[p + 1][1], wr[4], a);
                a = fmaf(vv[p + 1][2], wr[5], a);
                a = fmaf(vv[p + 2][0], wr[6], a);
                a = fmaf(vv[p + 2][1], wr[7], a);
                a = fmaf(vv[p + 2][2], wr[8], a);
                acc[p][o] = a;
            }
        }
        __syncthreads();
    }

#pragma unroll
    for (int o = 0; o < 8; o++) {
        float bb = bias[coB + o];
#pragma unroll
        for (int p = 0; p < 4; p++) {
            float r = acc[p][o] + bb;
            if (LRELU) r = (r >= 0.f) ? r : 0.1f * r;
            int oy = y0 + ty4 + p;
            if (PADOUT)
                out[(coB + o) * PS + (oy + 1) * PW + x0 + tx + 1] = r;
            else
                out[(coB + o) * HWN + oy * WW + x0 + tx] = r;
        }
    }
}

// ---------------- conv 3x3, CIN=64: 2 cins per sync step, 6x3 window ---------------
template <bool LRELU>
__global__ __launch_bounds__(128) void conv3x3_c64_kernel(
    const float* __restrict__ in, const float* __restrict__ wgt,
    const float* __restrict__ bias, float* __restrict__ out)
{
    __shared__ float s_in[2][2][18][34];            // [buf][cc][r][c]  19.6 KB
    __shared__ __align__(16) float s_w[64][8][12];  // 24.6 KB

    const int tid = threadIdx.x;
    const int tx = tid & 31;
    const int ty4 = (tid >> 5) * 4;
    const int x0 = blockIdx.x * 32;
    const int y0 = blockIdx.y * 16;
    const int coB = blockIdx.z * 8;

    for (int i = tid; i < 64 * 8 * 9; i += 128) {
        int co = i / (64 * 9);
        int r = i - co * (64 * 9);
        s_w[r / 9][co][r % 9] = wgt[(coB + co) * (64 * 9) + r];
    }
    stage_tile_padded(s_in[0][0], in + y0 * PW + x0, tid);
    stage_tile_padded(s_in[0][1], in + PS + y0 * PW + x0, tid);
    __syncthreads();

    float acc[4][8];
#pragma unroll
    for (int p = 0; p < 4; p++)
#pragma unroll
        for (int o = 0; o < 8; o++) acc[p][o] = 0.f;

    for (int cp = 0; cp < 32; cp++) {
        const int pb = cp & 1;
        if (cp + 1 < 32) {
            const float* ip = in + (2 * cp + 2) * PS + y0 * PW + x0;
            stage_tile_padded(s_in[1 - pb][0], ip, tid);
            stage_tile_padded(s_in[1 - pb][1], ip + PS, tid);
        }
#pragma unroll
        for (int cc = 0; cc < 2; cc++) {
            const int ci = 2 * cp + cc;
            float vv[6][3];
#pragma unroll
            for (int rr = 0; rr < 6; rr++)
#pragma unroll
                for (int c = 0; c < 3; c++) vv[rr][c] = s_in[pb][cc][ty4 + rr][tx + c];
#pragma unroll
            for (int o = 0; o < 8; o++) {
                const float4* wv4 = reinterpret_cast<const float4*>(&s_w[ci][o][0]);
                float4 w0 = wv4[0], w1 = wv4[1], w2 = wv4[2];
#pragma unroll
                for (int p = 0; p < 4; p++) {
                    float a = acc[p][o];
                    a = fmaf(vv[p + 0][0], w0.x, a);
                    a = fmaf(vv[p + 0][1], w0.y, a);
                    a = fmaf(vv[p + 0][2], w0.z, a);
                    a = fmaf(vv[p + 1][0], w0.w, a);
                    a = fmaf(vv[p + 1][1], w1.x, a);
                    a = fmaf(vv[p + 1][2], w1.y, a);
                    a = fmaf(vv[p + 2][0], w1.z, a);
                    a = fmaf(vv[p + 2][1], w1.w, a);
                    a = fmaf(vv[p + 2][2], w2.x, a);
                    acc[p][o] = a;
                }
            }
        }
        __syncthreads();
    }

#pragma unroll
    for (int o = 0; o < 8; o++) {
        float bb = bias[coB + o];
#pragma unroll
        for (int p = 0; p < 4; p++) {
            float r = acc[p][o] + bb;
            if (LRELU) r = (r >= 0.f) ? r : 0.1f * r;
            int oy = y0 + ty4 + p;
            out[(coB + o) * PS + (oy + 1) * PW + x0 + tx + 1] = r;
        }
    }
}

// ---------------- weight transpose for mdcn: wT[k][cin][o] = w[o][cin][k] ----------
__global__ void transpose_w_kernel(const float* __restrict__ wsrc, float* __restrict__ wT)
{
    int i = blockIdx.x * 256 + threadIdx.x;
    if (i < 9 * 4096) {
        int k = i / 4096;
        int r = i - k * 4096;
        int ci = r >> 6;
        int o = r & 63;
        wT[i] = wsrc[(o * 64 + ci) * 9 + k];
    }
}

__device__ __forceinline__ float fast_tanh(float x)
{
    x = fminf(fmaxf(x, -15.f), 15.f);
    float e = __expf(2.f * x);
    return (e - 1.f) / (e + 1.f);
}

// ---------------- modulated deformable conv (fused offset transform) --------------
__global__ __launch_bounds__(128) void mdcn_kernel(
    const float* __restrict__ x, const float* __restrict__ co,
    const float* __restrict__ flow, const float* __restrict__ wT,
    const float* __restrict__ bias, float* __restrict__ out)
{
    __shared__ __align__(16) float s_w[4096];
    const int tid = threadIdx.x;
    const int px = blockIdx.x * 32 + (tid & 31);
    const int pyi = blockIdx.y * 4 + (tid >> 5);
    const int pix = pyi * WW + px;
    const int ppix = (pyi + 1) * PW + px + 1;

    const float f0 = flow[pix];
    const float f1 = flow[HWN + pix];

    float acc[64];
#pragma unroll
    for (int o = 0; o < 64; o++) acc[o] = 0.f;

#pragma unroll 1
    for (int k = 0; k < 9; k++) {
        __syncthreads();
        {
            const float4* src = reinterpret_cast<const float4*>(wT + k * 4096);
            float4* dst = reinterpret_cast<float4*>(s_w);
            for (int i = tid; i < 1024; i += 128) dst[i] = src[i];
        }
        __syncthreads();
        const float kyf = (float)(k / 3 - 1);
        const float kxf = (float)(k % 3 - 1);
#pragma unroll 1
        for (int g = 0; g < 8; g++) {
            float oy = 10.f * fast_tanh(co[(g * 18 + 2 * k) * PS + ppix]) + f1;
            float ox = 10.f * fast_tanh(co[(g * 18 + 2 * k + 1) * PS + ppix]) + f0;
            float mr = co[(144 + g * 9 + k) * PS + ppix];
            float mv = 1.f / (1.f + __expf(-mr));

            float pyf = (float)pyi + kyf + oy;
            float pxf = (float)px + kxf + ox;
            float y0f = floorf(pyf), x0f = floorf(pxf);
            float ly = pyf - y0f, lx = pxf - x0f;
            int iy0 = (int)y0f, ix0 = (int)x0f;
            int iy1 = iy0 + 1, ix1 = ix0 + 1;
            bool vy0 = (iy0 >= 0) & (iy0 < HH);
            bool vy1 = (iy1 >= 0) & (iy1 < HH);
            bool vx0 = (ix0 >= 0) & (ix0 < WW);
            bool vx1 = (ix1 >= 0) & (ix1 < WW);
            int cy0 = min(max(iy0, 0), HH - 1), cy1 = min(max(iy1, 0), HH - 1);
            int cx0 = min(max(ix0, 0), WW - 1), cx1 = min(max(ix1, 0), WW - 1);
            float w00 = (1.f - ly) * (1.f - lx) * mv;
            float w01 = (1.f - ly) * lx * mv;
            float w10 = ly * (1.f - lx) * mv;
            float w11 = ly * lx * mv;
            int i00 = cy0 * WW + cx0, i01 = cy0 * WW + cx1;
            int i10 = cy1 * WW + cx0, i11 = cy1 * WW + cx1;

#pragma unroll
            for (int c4 = 0; c4 < 2; c4++) {
                float v00[4], v01[4], v10[4], v11[4];
#pragma unroll
                for (int j = 0; j < 4; j++) {
                    const float* xc = x + (g * 8 + c4 * 4 + j) * HWN;
                    v00[j] = (vy0 && vx0) ? xc[i00] : 0.f;
                    v01[j] = (vy0 && vx1) ? xc[i01] : 0.f;
                    v10[j] = (vy1 && vx0) ? xc[i10] : 0.f;
                    v11[j] = (vy1 && vx1) ? xc[i11] : 0.f;
                }
#pragma unroll
                for (int j = 0; j < 4; j++) {
                    float s = v00[j] * w00 + v01[j] * w01 + v10[j] * w10 + v11[j] * w11;
                    const float4* wp =
                        reinterpret_cast<const float4*>(&s_w[(g * 8 + c4 * 4 + j) * 64]);
#pragma unroll
                    for (int q = 0; q < 16; q++) {
                        float4 wv = wp[q];
                        acc[4 * q + 0] = fmaf(wv.x, s, acc[4 * q + 0]);
                        acc[4 * q + 1] = fmaf(wv.y, s, acc[4 * q + 1]);
                        acc[4 * q + 2] = fmaf(wv.z, s, acc[4 * q + 2]);
                        acc[4 * q + 3] = fmaf(wv.w, s, acc[4 * q + 3]);
                    }
                }
            }
        }
    }
#pragma unroll
    for (int o = 0; o < 64; o++) out[o * PS + ppix] = acc[o] + bias[o];
}

// ---------------- launch ----------------
extern "C" void kernel_launch(void* const* d_in, const int* in_sizes, int n_in,
                              void* d_out, int out_size)
{
    (void)in_sizes; (void)n_in; (void)out_size;
    const float* feat_prev = (const float*)d_in[0];
    const float* feat_next = (const float*)d_in[1];
    const float* extra_prev = (const float*)d_in[2];
    const float* extra_next = (const float*)d_in[3];
    const float* flow_prev = (const float*)d_in[4];
    const float* flow_next = (const float*)d_in[5];
    const float* dcn1_w = (const float*)d_in[22];
    const float* dcn1_b = (const float*)d_in[23];
    const float* dcn2_w = (const float*)d_in[24];
    const float* dcn2_b = (const float*)d_in[25];
    const float* fus_w = (const float*)d_in[26];
    const float* fus_b = (const float*)d_in[27];
    float* out = (float*)d_out;

    float *t0, *t1, *c3, *cat, *wT;
    cudaGetSymbolAddress((void**)&t0, g_t0);
    cudaGetSymbolAddress((void**)&t1, g_t1);
    cudaGetSymbolAddress((void**)&c3, g_c3);
    cudaGetSymbolAddress((void**)&cat, g_cat);
    cudaGetSymbolAddress((void**)&wT, g_wT);

    dim3 blk(128);
    dim3 g64(8, 16, 8);
    dim3 g216(8, 16, 27);

    // transposes first so ncu -s 5 lands on conv4 (branch 0, launch #6)
    transpose_w_kernel<<<144, 256>>>(dcn1_w, wT);
    transpose_w_kernel<<<144, 256>>>(dcn1_w, wT);

    for (int br = 0; br < 2; br++) {
        const float* feat = br == 0 ? feat_prev : feat_next;
        const float* extra = br == 0 ? extra_prev : extra_next;
        const float* flow = br == 0 ? flow_prev : flow_next;
        const float* w0 = (const float*)d_in[6 + 8 * br + 0];
        const float* b0 = (const float*)d_in[6 + 8 * br + 1];
        const float* w1 = (const float*)d_in[6 + 8 * br + 2];
        const float* b1 = (const float*)d_in[6 + 8 * br + 3];
        const float* w2 = (const float*)d_in[6 + 8 * br + 4];
        const float* b2 = (const float*)d_in[6 + 8 * br + 5];
        const float* w3 = (const float*)d_in[6 + 8 * br + 6];
        const float* b3 = (const float*)d_in[6 + 8 * br + 7];
        const float* dw = br == 0 ? dcn1_w : dcn2_w;
        const float* db = br == 0 ? dcn1_b : dcn2_b;

        conv3x3_c128_kernel<true, true, true><<<g64, blk>>>(extra, w0, b0, t0);
        conv3x3_c64_kernel<true><<<g64, blk>>>(t0, w1, b1, t1);
        conv3x3_c64_kernel<true><<<g64, blk>>>(t1, w2, b2, t0);
        conv3x3_c64_kernel<false><<<g216, blk>>>(t0, w3, b3, c3);
        transpose_w_kernel<<<144, 256>>>(dw, wT);
        mdcn_kernel<<<dim3(8, 64), blk>>>(feat, c3, flow, wT, db, cat + br * 64 * PS);
    }
    conv3x3_c128_kernel<false, false, false><<<g64, blk>>>(cat, fus_w, fus_b, out);
}